// round 5
// baseline (speedup 1.0000x reference)
#include <cuda_runtime.h>
#include <cstdint>

#define BDIM 256
#define FDIM 4
#define MDIM 256
#define DDIM 8192
#define NITERS 10

// Scratch (device globals -- allocation is forbidden)
__device__ float g_est[BDIM * FDIM * DDIM];   // 32 MB
__device__ float g_new[BDIM * FDIM * DDIM];   // 32 MB
__device__ float g_sim[BDIM * FDIM * MDIM];   // 1 MB
__device__ int g_done;
__device__ int g_diff;
__device__ int g_k;

// ---------------------------------------------------------------------------
// init: est[b,f,d] = sum_m cb[f,m,d]; also reset flags (block 0, thread 0)
// ---------------------------------------------------------------------------
__global__ void init_est_kernel(const float* __restrict__ cb) {
    int idx = blockIdx.x * blockDim.x + threadIdx.x;
    if (idx == 0) { g_done = 0; g_diff = 0; g_k = 0; }
    if (idx >= FDIM * DDIM) return;
    int f = idx >> 13;
    int d = idx & (DDIM - 1);
    const float* p = cb + ((size_t)f * MDIM) * DDIM + d;
    float s = 0.f;
    for (int m = 0; m < MDIM; m++) s += p[(size_t)m * DDIM];
    float* q = g_est + (size_t)f * DDIM + d;
    for (int b = 0; b < BDIM; b++) q[(size_t)b * FDIM * DDIM] = s;
}

// ---------------------------------------------------------------------------
__global__ void zero_sim_kernel() {
    int idx = blockIdx.x * blockDim.x + threadIdx.x;
    if (idx < BDIM * FDIM * MDIM) g_sim[idx] = 0.f;
}

// ---------------------------------------------------------------------------
// new_est[b,f,d] = inp[b,d] * prod_{f' != f} est[b,f',d]
// ---------------------------------------------------------------------------
__global__ void newest_kernel(const float* __restrict__ inp) {
    if (g_done) return;
    int idx = blockIdx.x * blockDim.x + threadIdx.x;   // b*8192 + d
    int b = idx >> 13;
    int d = idx & (DDIM - 1);
    const float* eb = g_est + ((size_t)b * FDIM) * DDIM + d;
    float e0 = eb[0];
    float e1 = eb[DDIM];
    float e2 = eb[2 * DDIM];
    float e3 = eb[3 * DDIM];
    float x = inp[idx];
    float p01 = e0 * e1;
    float p23 = e2 * e3;
    float* nb = g_new + ((size_t)b * FDIM) * DDIM + d;
    nb[0]        = x * (e1 * p23);
    nb[DDIM]     = x * (e0 * p23);
    nb[2 * DDIM] = x * (p01 * e3);
    nb[3 * DDIM] = x * (p01 * e2);
}

// ---------------------------------------------------------------------------
// GEMM1: sim[b,f,m] += sum_d A[b,f,d]*cb[f,m,d]   split-K=8 via atomicAdd.
// grid: x = 16 (bt*4+mt), y = f, z = 8.  block 256.  tile 64x64, micro 4x4.
// Exact: all partials are integers (divisible by 8, |.| < 2^27) in fp32.
// ---------------------------------------------------------------------------
__global__ void gemm1_kernel(const float* __restrict__ cb, int use_new, int respect_done) {
    if (respect_done && g_done) return;
    const float* A = use_new ? g_new : g_est;
    int bt = blockIdx.x >> 2;
    int mt = blockIdx.x & 3;
    int f = blockIdx.y;
    int b0 = bt * 64;
    int m0 = mt * 64;
    int k0 = blockIdx.z * (DDIM / 8);      // 1024 per z-slice

    __shared__ float As[32][68];           // [k][b]
    __shared__ float Bs[32][68];           // [k][m]

    int tx = threadIdx.x & 15;             // b-group
    int ty = threadIdx.x >> 4;             // m-group

    float acc[4][4];
    for (int i = 0; i < 4; i++)
        for (int j = 0; j < 4; j++) acc[i][j] = 0.f;

    for (int kk = 0; kk < DDIM / 8; kk += 32) {
        for (int e = threadIdx.x; e < 2048; e += 256) {
            int r = e >> 5;                // 0..63 (b or m)
            int c = e & 31;                // 0..31 (k)
            As[c][r] = A[((size_t)(b0 + r) * FDIM + f) * DDIM + k0 + kk + c];
            Bs[c][r] = cb[((size_t)f * MDIM + m0 + r) * DDIM + k0 + kk + c];
        }
        __syncthreads();
        #pragma unroll
        for (int k = 0; k < 32; k++) {
            float a0 = As[k][tx * 4 + 0];
            float a1 = As[k][tx * 4 + 1];
            float a2 = As[k][tx * 4 + 2];
            float a3 = As[k][tx * 4 + 3];
            float c0 = Bs[k][ty * 4 + 0];
            float c1 = Bs[k][ty * 4 + 1];
            float c2 = Bs[k][ty * 4 + 2];
            float c3 = Bs[k][ty * 4 + 3];
            acc[0][0] += a0 * c0; acc[0][1] += a0 * c1; acc[0][2] += a0 * c2; acc[0][3] += a0 * c3;
            acc[1][0] += a1 * c0; acc[1][1] += a1 * c1; acc[1][2] += a1 * c2; acc[1][3] += a1 * c3;
            acc[2][0] += a2 * c0; acc[2][1] += a2 * c1; acc[2][2] += a2 * c2; acc[2][3] += a2 * c3;
            acc[3][0] += a3 * c0; acc[3][1] += a3 * c1; acc[3][2] += a3 * c2; acc[3][3] += a3 * c3;
        }
        __syncthreads();
    }
    for (int i = 0; i < 4; i++)
        for (int j = 0; j < 4; j++) {
            int b = b0 + tx * 4 + i;
            int m = m0 + ty * 4 + j;
            atomicAdd(&g_sim[((size_t)b * FDIM + f) * MDIM + m], acc[i][j]);
        }
}

// ---------------------------------------------------------------------------
// GEMM2 + sign + convergence compare + est update.
// ---------------------------------------------------------------------------
__global__ void gemm2_kernel(const float* __restrict__ cb) {
    if (g_done) return;
    int f = blockIdx.z;
    int b0 = blockIdx.y * 64;
    int d0 = blockIdx.x * 64;

    __shared__ float As[32][68];    // [m][b]
    __shared__ float Bs[32][68];    // [m][d]

    int tx = threadIdx.x & 15;      // d-group
    int ty = threadIdx.x >> 4;      // b-group

    float acc[4][4];
    for (int i = 0; i < 4; i++)
        for (int j = 0; j < 4; j++) acc[i][j] = 0.f;

    for (int mb = 0; mb < MDIM; mb += 32) {
        for (int e = threadIdx.x; e < 2048; e += 256) {
            int r = e >> 5;         // 0..63 (b)
            int c = e & 31;         // 0..31 (m)
            As[c][r] = g_sim[((size_t)(b0 + r) * FDIM + f) * MDIM + mb + c];
        }
        for (int e = threadIdx.x; e < 2048; e += 256) {
            int m = e >> 6;         // 0..31
            int dd = e & 63;        // 0..63
            Bs[m][dd] = cb[((size_t)f * MDIM + mb + m) * DDIM + d0 + dd];
        }
        __syncthreads();
        #pragma unroll
        for (int m = 0; m < 32; m++) {
            float a0 = As[m][ty * 4 + 0];
            float a1 = As[m][ty * 4 + 1];
            float a2 = As[m][ty * 4 + 2];
            float a3 = As[m][ty * 4 + 3];
            float c0 = Bs[m][tx * 4 + 0];
            float c1 = Bs[m][tx * 4 + 1];
            float c2 = Bs[m][tx * 4 + 2];
            float c3 = Bs[m][tx * 4 + 3];
            acc[0][0] += a0 * c0; acc[0][1] += a0 * c1; acc[0][2] += a0 * c2; acc[0][3] += a0 * c3;
            acc[1][0] += a1 * c0; acc[1][1] += a1 * c1; acc[1][2] += a1 * c2; acc[1][3] += a1 * c3;
            acc[2][0] += a2 * c0; acc[2][1] += a2 * c1; acc[2][2] += a2 * c2; acc[2][3] += a2 * c3;
            acc[3][0] += a3 * c0; acc[3][1] += a3 * c1; acc[3][2] += a3 * c2; acc[3][3] += a3 * c3;
        }
        __syncthreads();
    }

    int ldiff = 0;
    for (int i = 0; i < 4; i++) {
        int b = b0 + ty * 4 + i;
        float* erow = g_est + ((size_t)b * FDIM + f) * DDIM + d0 + tx * 4;
        for (int j = 0; j < 4; j++) {
            float v = acc[i][j];
            float s = (v > 0.f) ? 1.f : ((v < 0.f) ? -1.f : 0.f);
            if (s != erow[j]) ldiff = 1;
            erow[j] = s;
        }
    }
    if (ldiff) g_diff = 1;
}

// ---------------------------------------------------------------------------
__global__ void step_kernel() {
    if (g_done) return;
    g_k = g_k + 1;
    if (g_diff == 0) g_done = 1;
    g_diff = 0;
}

// ---------------------------------------------------------------------------
// argmax over m (first-index tie-break) + write k.  One warp per (b,f).
// OUTPUT AS FLOAT32: the harness's __output__ dtype for this problem is
// float32 (flattened (outcome, k)); argmax indices (<=255) and k (<=10) are
// exactly representable.
// ---------------------------------------------------------------------------
__global__ void argmax_kernel(float* __restrict__ out, int out_size) {
    int gtid = blockIdx.x * blockDim.x + threadIdx.x;
    int w = gtid >> 5;
    int lane = gtid & 31;
    if (w < BDIM * FDIM) {
        const float* srow = g_sim + (size_t)w * MDIM;
        float bv = -3.0e38f;
        int bi = 0;
        for (int m = lane; m < MDIM; m += 32) {
            float v = srow[m];
            if (v > bv) { bv = v; bi = m; }
        }
        for (int off = 16; off > 0; off >>= 1) {
            float ov = __shfl_down_sync(0xffffffffu, bv, off);
            int oi = __shfl_down_sync(0xffffffffu, bi, off);
            if (ov > bv || (ov == bv && oi < bi)) { bv = ov; bi = oi; }
        }
        if (lane == 0) out[w] = (float)bi;
    }
    if (gtid == 0 && out_size > BDIM * FDIM) out[BDIM * FDIM] = (float)g_k;
}

// ---------------------------------------------------------------------------
extern "C" void kernel_launch(void* const* d_in, const int* in_sizes, int n_in,
                              void* d_out, int out_size) {
    // codebooks buffer is strictly larger than input (elements or bytes).
    const float* inp;
    const float* cb;
    if (in_sizes[0] < in_sizes[1]) { inp = (const float*)d_in[0]; cb = (const float*)d_in[1]; }
    else                           { inp = (const float*)d_in[1]; cb = (const float*)d_in[0]; }
    float* out = (float*)d_out;

    init_est_kernel<<<(FDIM * DDIM + 255) / 256, 256>>>(cb);

    for (int it = 0; it < NITERS; it++) {
        zero_sim_kernel<<<(BDIM * FDIM * MDIM) / 256, 256>>>();
        newest_kernel<<<(BDIM * DDIM) / 256, 256>>>(inp);
        gemm1_kernel<<<dim3(16, FDIM, 8), 256>>>(cb, /*use_new=*/1, /*respect_done=*/1);
        gemm2_kernel<<<dim3(DDIM / 64, BDIM / 64, FDIM), 256>>>(cb);
        step_kernel<<<1, 1>>>();
    }

    // Final similarity from converged est, then argmax + k
    zero_sim_kernel<<<(BDIM * FDIM * MDIM) / 256, 256>>>();
    gemm1_kernel<<<dim3(16, FDIM, 8), 256>>>(cb, /*use_new=*/0, /*respect_done=*/0);
    argmax_kernel<<<(BDIM * FDIM * 32) / 256, 256>>>(out, out_size);
}

// round 6
// speedup vs baseline: 2.8852x; 2.8852x over previous
#include <cuda_runtime.h>
#include <cstdint>

#define BDIM 256
#define FDIM 4
#define MDIM 256
#define DDIM 8192
#define WDIM 256          // DDIM/32 packed words
#define NITERS 10

// Scratch (device globals -- allocation is forbidden)
__device__ float g_est[BDIM * FDIM * DDIM];   // 32 MB  current estimate (float +-1/0 after stage0)
__device__ float g_new[BDIM * FDIM * DDIM];   // 32 MB  stage-0 new_est (large-valued)
__device__ float g_sim[BDIM * FDIM * MDIM];   // 1 MB
__device__ unsigned g_pS[BDIM * FDIM * WDIM]; // 1 MB   packed sign bits (new_est or est)
__device__ unsigned g_pM[BDIM * FDIM * WDIM]; // 1 MB   packed nonzero mask
__device__ unsigned g_cbSt[FDIM * WDIM * MDIM]; // 1 MB cb sign bits transposed [f][w][m]
__device__ signed char g_cbT8[FDIM * DDIM * MDIM]; // 8 MB cb int8 transposed [f][d][m]
__device__ signed char g_simLo[BDIM * FDIM * MDIM]; // sim low plane
__device__ signed char g_simHi[BDIM * FDIM * MDIM]; // sim high plane (sim = 128*hi + lo)
__device__ int g_done;
__device__ int g_diff;
__device__ int g_k;

// ---------------------------------------------------------------------------
// init: est[b,f,d] = sum_m cb[f,m,d]; also reset flags
// ---------------------------------------------------------------------------
__global__ void init_est_kernel(const float* __restrict__ cb) {
    int idx = blockIdx.x * blockDim.x + threadIdx.x;
    if (idx == 0) { g_done = 0; g_diff = 0; g_k = 0; }
    if (idx >= FDIM * DDIM) return;
    int f = idx >> 13;
    int d = idx & (DDIM - 1);
    const float* p = cb + ((size_t)f * MDIM) * DDIM + d;
    float s = 0.f;
    for (int m = 0; m < MDIM; m++) s += p[(size_t)m * DDIM];
    float* q = g_est + (size_t)f * DDIM + d;
    for (int b = 0; b < BDIM; b++) q[(size_t)b * FDIM * DDIM] = s;
}

// ---------------------------------------------------------------------------
// pack cb sign bits (cb is strictly +-1): g_cbSt[f][w][m], bit j of word w <-> d = w*32+j, bit=1 means negative
// ---------------------------------------------------------------------------
__global__ void pack_cb_kernel(const float* __restrict__ cb) {
    int idx = blockIdx.x * blockDim.x + threadIdx.x;  // (f*M+m)*8192 + d
    float v = cb[idx];
    unsigned neg = __ballot_sync(0xffffffffu, v < 0.f);
    if ((threadIdx.x & 31) == 0) {
        int fm = idx >> 13;
        int d = idx & (DDIM - 1);
        int f = fm >> 8;
        int m = fm & 255;
        g_cbSt[((size_t)f * WDIM + (d >> 5)) * MDIM + m] = neg;
    }
}

// ---------------------------------------------------------------------------
// cb -> int8 transposed [f][d][m]  (32x32 tile transpose via smem)
// grid (D/32, M/32, F), block 256 (32 x 8)
// ---------------------------------------------------------------------------
__global__ void cb_t8_kernel(const float* __restrict__ cb) {
    __shared__ signed char t[32][33];
    int d0 = blockIdx.x * 32;
    int m0 = blockIdx.y * 32;
    int f = blockIdx.z;
    int tx = threadIdx.x & 31;
    int ty = threadIdx.x >> 5;    // 0..7
    for (int k = 0; k < 4; k++) {
        int m = m0 + ty * 4 + k;
        t[ty * 4 + k][tx] = (signed char)cb[((size_t)f * MDIM + m) * DDIM + d0 + tx];
    }
    __syncthreads();
    for (int k = 0; k < 4; k++) {
        int d = d0 + ty * 4 + k;
        g_cbT8[((size_t)f * DDIM + d) * MDIM + m0 + tx] = t[tx][ty * 4 + k];
    }
}

// ---------------------------------------------------------------------------
__global__ void zero_sim_kernel() {
    int idx = blockIdx.x * blockDim.x + threadIdx.x;
    if (idx < BDIM * FDIM * MDIM) g_sim[idx] = 0.f;
}

// ---------------------------------------------------------------------------
// stage-0 new_est (float, large values)
// ---------------------------------------------------------------------------
__global__ void newest_f32_kernel(const float* __restrict__ inp) {
    if (g_done) return;
    int idx = blockIdx.x * blockDim.x + threadIdx.x;   // b*8192 + d
    int b = idx >> 13;
    int d = idx & (DDIM - 1);
    const float* eb = g_est + ((size_t)b * FDIM) * DDIM + d;
    float e0 = eb[0];
    float e1 = eb[DDIM];
    float e2 = eb[2 * DDIM];
    float e3 = eb[3 * DDIM];
    float x = inp[idx];
    float p01 = e0 * e1;
    float p23 = e2 * e3;
    float* nb = g_new + ((size_t)b * FDIM) * DDIM + d;
    nb[0]        = x * (e1 * p23);
    nb[DDIM]     = x * (e0 * p23);
    nb[2 * DDIM] = x * (p01 * e3);
    nb[3 * DDIM] = x * (p01 * e2);
}

// ---------------------------------------------------------------------------
// stages >=1: packed new_est.  est is ternary float, inp is +-1 float.
// bit lane = d & 31.  canonical: sign bit only where mask set.
// ---------------------------------------------------------------------------
__global__ void newest_packed_kernel(const float* __restrict__ inp) {
    if (g_done) return;
    int idx = blockIdx.x * blockDim.x + threadIdx.x;   // b*8192 + d
    int b = idx >> 13;
    int d = idx & (DDIM - 1);
    const float* eb = g_est + ((size_t)b * FDIM) * DDIM + d;
    float e0 = eb[0];
    float e1 = eb[DDIM];
    float e2 = eb[2 * DDIM];
    float e3 = eb[3 * DDIM];
    float x = inp[idx];
    float p01 = e0 * e1;
    float p23 = e2 * e3;
    float v[4];
    v[0] = x * (e1 * p23);
    v[1] = x * (e0 * p23);
    v[2] = x * (p01 * e3);
    v[3] = x * (p01 * e2);
    int lane = threadIdx.x & 31;
    #pragma unroll
    for (int f = 0; f < 4; f++) {
        unsigned neg = __ballot_sync(0xffffffffu, v[f] < 0.f);
        unsigned nzm = __ballot_sync(0xffffffffu, v[f] != 0.f);
        if (lane == 0) {
            size_t w = ((size_t)b * FDIM + f) * WDIM + (d >> 5);
            g_pS[w] = neg & nzm;
            g_pM[w] = nzm;
        }
    }
}

// ---------------------------------------------------------------------------
// pack current est (ternary float) into g_pS/g_pM (for the final sim)
// ---------------------------------------------------------------------------
__global__ void est_pack_kernel() {
    int idx = blockIdx.x * blockDim.x + threadIdx.x;   // (b*F+f)*8192 + d
    float v = g_est[idx];
    unsigned neg = __ballot_sync(0xffffffffu, v < 0.f);
    unsigned nzm = __ballot_sync(0xffffffffu, v != 0.f);
    if ((threadIdx.x & 31) == 0) {
        int bf = idx >> 13;
        int d = idx & (DDIM - 1);
        g_pS[(size_t)bf * WDIM + (d >> 5)] = neg & nzm;
        g_pM[(size_t)bf * WDIM + (d >> 5)] = nzm;
    }
}

// ---------------------------------------------------------------------------
// stage-0 GEMM1 (float, split-K=8 atomicAdd) -- proven, unchanged
// ---------------------------------------------------------------------------
__global__ void gemm1_f32_kernel(const float* __restrict__ cb) {
    if (g_done) return;
    const float* A = g_new;
    int bt = blockIdx.x >> 2;
    int mt = blockIdx.x & 3;
    int f = blockIdx.y;
    int b0 = bt * 64;
    int m0 = mt * 64;
    int k0 = blockIdx.z * (DDIM / 8);

    __shared__ float As[32][68];
    __shared__ float Bs[32][68];

    int tx = threadIdx.x & 15;
    int ty = threadIdx.x >> 4;

    float acc[4][4];
    for (int i = 0; i < 4; i++)
        for (int j = 0; j < 4; j++) acc[i][j] = 0.f;

    for (int kk = 0; kk < DDIM / 8; kk += 32) {
        for (int e = threadIdx.x; e < 2048; e += 256) {
            int r = e >> 5;
            int c = e & 31;
            As[c][r] = A[((size_t)(b0 + r) * FDIM + f) * DDIM + k0 + kk + c];
            Bs[c][r] = cb[((size_t)f * MDIM + m0 + r) * DDIM + k0 + kk + c];
        }
        __syncthreads();
        #pragma unroll
        for (int k = 0; k < 32; k++) {
            float a0 = As[k][tx * 4 + 0];
            float a1 = As[k][tx * 4 + 1];
            float a2 = As[k][tx * 4 + 2];
            float a3 = As[k][tx * 4 + 3];
            float c0 = Bs[k][ty * 4 + 0];
            float c1 = Bs[k][ty * 4 + 1];
            float c2 = Bs[k][ty * 4 + 2];
            float c3 = Bs[k][ty * 4 + 3];
            acc[0][0] += a0 * c0; acc[0][1] += a0 * c1; acc[0][2] += a0 * c2; acc[0][3] += a0 * c3;
            acc[1][0] += a1 * c0; acc[1][1] += a1 * c1; acc[1][2] += a1 * c2; acc[1][3] += a1 * c3;
            acc[2][0] += a2 * c0; acc[2][1] += a2 * c1; acc[2][2] += a2 * c2; acc[2][3] += a2 * c3;
            acc[3][0] += a3 * c0; acc[3][1] += a3 * c1; acc[3][2] += a3 * c2; acc[3][3] += a3 * c3;
        }
        __syncthreads();
    }
    for (int i = 0; i < 4; i++)
        for (int j = 0; j < 4; j++) {
            int b = b0 + tx * 4 + i;
            int m = m0 + ty * 4 + j;
            atomicAdd(&g_sim[((size_t)b * FDIM + f) * MDIM + m], acc[i][j]);
        }
}

// ---------------------------------------------------------------------------
// stage-0 GEMM2 (float) + sign + convergence + est update -- proven, unchanged
// ---------------------------------------------------------------------------
__global__ void gemm2_f32_kernel(const float* __restrict__ cb) {
    if (g_done) return;
    int f = blockIdx.z;
    int b0 = blockIdx.y * 64;
    int d0 = blockIdx.x * 64;

    __shared__ float As[32][68];
    __shared__ float Bs[32][68];

    int tx = threadIdx.x & 15;
    int ty = threadIdx.x >> 4;

    float acc[4][4];
    for (int i = 0; i < 4; i++)
        for (int j = 0; j < 4; j++) acc[i][j] = 0.f;

    for (int mb = 0; mb < MDIM; mb += 32) {
        for (int e = threadIdx.x; e < 2048; e += 256) {
            int r = e >> 5;
            int c = e & 31;
            As[c][r] = g_sim[((size_t)(b0 + r) * FDIM + f) * MDIM + mb + c];
        }
        for (int e = threadIdx.x; e < 2048; e += 256) {
            int m = e >> 6;
            int dd = e & 63;
            Bs[m][dd] = cb[((size_t)f * MDIM + mb + m) * DDIM + d0 + dd];
        }
        __syncthreads();
        #pragma unroll
        for (int m = 0; m < 32; m++) {
            float a0 = As[m][ty * 4 + 0];
            float a1 = As[m][ty * 4 + 1];
            float a2 = As[m][ty * 4 + 2];
            float a3 = As[m][ty * 4 + 3];
            float c0 = Bs[m][tx * 4 + 0];
            float c1 = Bs[m][tx * 4 + 1];
            float c2 = Bs[m][tx * 4 + 2];
            float c3 = Bs[m][tx * 4 + 3];
            acc[0][0] += a0 * c0; acc[0][1] += a0 * c1; acc[0][2] += a0 * c2; acc[0][3] += a0 * c3;
            acc[1][0] += a1 * c0; acc[1][1] += a1 * c1; acc[1][2] += a1 * c2; acc[1][3] += a1 * c3;
            acc[2][0] += a2 * c0; acc[2][1] += a2 * c1; acc[2][2] += a2 * c2; acc[2][3] += a2 * c3;
            acc[3][0] += a3 * c0; acc[3][1] += a3 * c1; acc[3][2] += a3 * c2; acc[3][3] += a3 * c3;
        }
        __syncthreads();
    }

    int ldiff = 0;
    for (int i = 0; i < 4; i++) {
        int b = b0 + ty * 4 + i;
        float* erow = g_est + ((size_t)b * FDIM + f) * DDIM + d0 + tx * 4;
        for (int j = 0; j < 4; j++) {
            float v = acc[i][j];
            float s = (v > 0.f) ? 1.f : ((v < 0.f) ? -1.f : 0.f);
            if (s != erow[j]) ldiff = 1;
            erow[j] = s;
        }
    }
    if (ldiff) g_diff = 1;
}

// ---------------------------------------------------------------------------
// packed GEMM1: sim[b,f,m] = nz - 2*popc((Sa ^ Sb) & Ma), summed over 256 words.
// grid (8 btiles, 8 mtiles, F), block 256.  tile 32x32, micro 2x2, K full.
// Writes g_sim (f32) and int8 planes (sim = 128*hi + lo).
// ---------------------------------------------------------------------------
__global__ void gemm1_packed_kernel(int respect_done) {
    if (respect_done && g_done) return;
    int b0 = blockIdx.x * 32;
    int m0 = blockIdx.y * 32;
    int f = blockIdx.z;

    __shared__ unsigned AS[32][33];   // [w][b]
    __shared__ unsigned AM[32][33];   // [w][b]
    __shared__ unsigned BS[32][33];   // [w][m]

    int tx = threadIdx.x & 15;        // b pair
    int ty = threadIdx.x >> 4;        // m pair

    int acc[2][2] = {{0, 0}, {0, 0}};
    int accM[2] = {0, 0};

    for (int w0 = 0; w0 < WDIM; w0 += 32) {
        for (int e = threadIdx.x; e < 1024; e += 256) {
            int r = e >> 5;           // b 0..31
            int c = e & 31;           // w 0..31
            size_t src = ((size_t)(b0 + r) * FDIM + f) * WDIM + w0 + c;
            AS[c][r] = g_pS[src];
            AM[c][r] = g_pM[src];
        }
        for (int e = threadIdx.x; e < 1024; e += 256) {
            int w = e >> 5;
            int m = e & 31;
            BS[w][m] = g_cbSt[((size_t)f * WDIM + w0 + w) * MDIM + m0 + m];
        }
        __syncthreads();
        #pragma unroll
        for (int w = 0; w < 32; w++) {
            unsigned sa0 = AS[w][tx * 2 + 0];
            unsigned sa1 = AS[w][tx * 2 + 1];
            unsigned ma0 = AM[w][tx * 2 + 0];
            unsigned ma1 = AM[w][tx * 2 + 1];
            unsigned sb0 = BS[w][ty * 2 + 0];
            unsigned sb1 = BS[w][ty * 2 + 1];
            accM[0] += __popc(ma0);
            accM[1] += __popc(ma1);
            acc[0][0] += __popc((sa0 ^ sb0) & ma0);
            acc[0][1] += __popc((sa0 ^ sb1) & ma0);
            acc[1][0] += __popc((sa1 ^ sb0) & ma1);
            acc[1][1] += __popc((sa1 ^ sb1) & ma1);
        }
        __syncthreads();
    }

    #pragma unroll
    for (int i = 0; i < 2; i++) {
        int b = b0 + tx * 2 + i;
        #pragma unroll
        for (int j = 0; j < 2; j++) {
            int m = m0 + ty * 2 + j;
            int sim = accM[i] - 2 * acc[i][j];
            size_t o = ((size_t)b * FDIM + f) * MDIM + m;
            g_sim[o] = (float)sim;
            int hi = (sim + 64) >> 7;       // arithmetic shift: hi in [-64,64]
            int lo = sim - (hi << 7);       // lo in [-64,63]
            g_simHi[o] = (signed char)hi;
            g_simLo[o] = (signed char)lo;
        }
    }
}

// ---------------------------------------------------------------------------
// packed GEMM2 via dp4a: out[b,f,d] = 128*(hi . cbT8[d]) + (lo . cbT8[d]) over m=256.
// grid (128 dtiles, 4 btiles, F), block 256.  tile 64d x 64b, micro 4x4,
// K = 64 int32 words in 2 chunks of 32.  Integer-exact (|out| <= 2^21).
// Epilogue identical semantics to gemm2_f32 (sign, compare, est update, diff).
// ---------------------------------------------------------------------------
__global__ void gemm2_dp4a_kernel() {
    if (g_done) return;
    int d0 = blockIdx.x * 64;
    int b0 = blockIdx.y * 64;
    int f = blockIdx.z;

    __shared__ int ALo[64][33];   // [b][w-chunk]
    __shared__ int AHi[64][33];
    __shared__ int Bc[64][33];    // [d][w-chunk]

    const int* simLoW = (const int*)g_simLo;
    const int* simHiW = (const int*)g_simHi;
    const int* cbW = (const int*)g_cbT8;

    int tx = threadIdx.x & 15;    // d group
    int ty = threadIdx.x >> 4;    // b group

    int accL[4][4];
    int accH[4][4];
    #pragma unroll
    for (int i = 0; i < 4; i++)
        #pragma unroll
        for (int j = 0; j < 4; j++) { accL[i][j] = 0; accH[i][j] = 0; }

    for (int w0 = 0; w0 < 64; w0 += 32) {
        for (int e = threadIdx.x; e < 2048; e += 256) {
            int r = e >> 5;        // 0..63
            int c = e & 31;        // 0..31
            size_t a = ((size_t)(b0 + r) * FDIM + f) * 64 + w0 + c;
            ALo[r][c] = simLoW[a];
            AHi[r][c] = simHiW[a];
            Bc[r][c] = cbW[((size_t)f * DDIM + d0 + r) * 64 + w0 + c];
        }
        __syncthreads();
        #pragma unroll
        for (int w = 0; w < 32; w++) {
            int al[4], ah[4], bb[4];
            #pragma unroll
            for (int i = 0; i < 4; i++) {
                al[i] = ALo[ty * 4 + i][w];
                ah[i] = AHi[ty * 4 + i][w];
            }
            #pragma unroll
            for (int j = 0; j < 4; j++) bb[j] = Bc[tx * 4 + j][w];
            #pragma unroll
            for (int i = 0; i < 4; i++)
                #pragma unroll
                for (int j = 0; j < 4; j++) {
                    accL[i][j] = __dp4a(al[i], bb[j], accL[i][j]);
                    accH[i][j] = __dp4a(ah[i], bb[j], accH[i][j]);
                }
        }
        __syncthreads();
    }

    int ldiff = 0;
    #pragma unroll
    for (int i = 0; i < 4; i++) {
        int b = b0 + ty * 4 + i;
        float* erow = g_est + ((size_t)b * FDIM + f) * DDIM + d0 + tx * 4;
        #pragma unroll
        for (int j = 0; j < 4; j++) {
            int out = accL[i][j] + (accH[i][j] << 7);
            float s = (out > 0) ? 1.f : ((out < 0) ? -1.f : 0.f);
            if (s != erow[j]) ldiff = 1;
            erow[j] = s;
        }
    }
    if (ldiff) g_diff = 1;
}

// ---------------------------------------------------------------------------
__global__ void step_kernel() {
    if (g_done) return;
    g_k = g_k + 1;
    if (g_diff == 0) g_done = 1;
    g_diff = 0;
}

// ---------------------------------------------------------------------------
// argmax over m (first-index tie-break) + write k.  Output dtype: float32.
// ---------------------------------------------------------------------------
__global__ void argmax_kernel(float* __restrict__ out, int out_size) {
    int gtid = blockIdx.x * blockDim.x + threadIdx.x;
    int w = gtid >> 5;
    int lane = gtid & 31;
    if (w < BDIM * FDIM) {
        const float* srow = g_sim + (size_t)w * MDIM;
        float bv = -3.0e38f;
        int bi = 0;
        for (int m = lane; m < MDIM; m += 32) {
            float v = srow[m];
            if (v > bv) { bv = v; bi = m; }
        }
        for (int off = 16; off > 0; off >>= 1) {
            float ov = __shfl_down_sync(0xffffffffu, bv, off);
            int oi = __shfl_down_sync(0xffffffffu, bi, off);
            if (ov > bv || (ov == bv && oi < bi)) { bv = ov; bi = oi; }
        }
        if (lane == 0) out[w] = (float)bi;
    }
    if (gtid == 0 && out_size > BDIM * FDIM) out[BDIM * FDIM] = (float)g_k;
}

// ---------------------------------------------------------------------------
extern "C" void kernel_launch(void* const* d_in, const int* in_sizes, int n_in,
                              void* d_out, int out_size) {
    const float* inp;
    const float* cb;
    if (in_sizes[0] < in_sizes[1]) { inp = (const float*)d_in[0]; cb = (const float*)d_in[1]; }
    else                           { inp = (const float*)d_in[1]; cb = (const float*)d_in[0]; }
    float* out = (float*)d_out;

    init_est_kernel<<<(FDIM * DDIM + 255) / 256, 256>>>(cb);
    pack_cb_kernel<<<(FDIM * MDIM * DDIM) / 256, 256>>>(cb);
    cb_t8_kernel<<<dim3(DDIM / 32, MDIM / 32, FDIM), 256>>>(cb);

    // ---- stage 0 (float path: new_est values are large, not ternary) ----
    zero_sim_kernel<<<(BDIM * FDIM * MDIM) / 256, 256>>>();
    newest_f32_kernel<<<(BDIM * DDIM) / 256, 256>>>(inp);
    gemm1_f32_kernel<<<dim3(16, FDIM, 8), 256>>>(cb);
    gemm2_f32_kernel<<<dim3(DDIM / 64, BDIM / 64, FDIM), 256>>>(cb);
    step_kernel<<<1, 1>>>();

    // ---- stages 1..9 (ternary packed path) ----
    for (int it = 1; it < NITERS; it++) {
        newest_packed_kernel<<<(BDIM * DDIM) / 256, 256>>>(inp);
        gemm1_packed_kernel<<<dim3(BDIM / 32, MDIM / 32, FDIM), 256>>>(1);
        gemm2_dp4a_kernel<<<dim3(DDIM / 64, BDIM / 64, FDIM), 256>>>();
        step_kernel<<<1, 1>>>();
    }

    // ---- final similarity from converged est, argmax + k ----
    est_pack_kernel<<<(BDIM * FDIM * DDIM) / 256, 256>>>();
    gemm1_packed_kernel<<<dim3(BDIM / 32, MDIM / 32, FDIM), 256>>>(0);
    argmax_kernel<<<(BDIM * FDIM * 32) / 256, 256>>>(out, out_size);
}